// round 10
// baseline (speedup 1.0000x reference)
#include <cuda_runtime.h>
#include <cstdint>

// Problem constants
#define CD    1024   // d_model
#define TQN   1024   // query tokens
#define NH    16     // heads
#define HD    64     // head dim
#define NKEY  512    // keys per head after HEPOS gather (8192/16)

// ---------------------------------------------------------------------------
// Scratch (device globals; runtime allocation is forbidden)
// ---------------------------------------------------------------------------
__device__ __align__(256) float g_Qp[TQN * CD];          // Q projection
__device__ __align__(256) float g_Kg[NH * NKEY * HD];    // gathered/projected K [h][j][d]
__device__ __align__(256) float g_Vg[NH * NKEY * HD];    // gathered/projected V [h][j][d]
__device__ __align__(256) float g_AO[TQN * CD];          // attention output

// ---------------------------------------------------------------------------
// mma.sync + cp.async helpers (legacy tensor-core path, base sm_100 target)
// ---------------------------------------------------------------------------
__device__ __forceinline__ uint32_t f2tf(float x) {
    uint32_t u;
    asm("cvt.rna.tf32.f32 %0, %1;" : "=r"(u) : "f"(x));
    return u;
}
__device__ __forceinline__ void mma8(float* c, const uint32_t* a, const uint32_t* b) {
    asm volatile(
        "mma.sync.aligned.m16n8k8.row.col.f32.tf32.tf32.f32 "
        "{%0,%1,%2,%3}, {%4,%5,%6,%7}, {%8,%9}, {%0,%1,%2,%3};\n"
        : "+f"(c[0]), "+f"(c[1]), "+f"(c[2]), "+f"(c[3])
        : "r"(a[0]), "r"(a[1]), "r"(a[2]), "r"(a[3]), "r"(b[0]), "r"(b[1]));
}
__device__ __forceinline__ void cp16(uint32_t dst, const void* src) {
    asm volatile("cp.async.ca.shared.global [%0], [%1], 16;"
                 :: "r"(dst), "l"(src));
}
__device__ __forceinline__ void cp_commit() { asm volatile("cp.async.commit_group;"); }
__device__ __forceinline__ void cp_wait0()  { asm volatile("cp.async.wait_group 0;" ::: "memory"); }
__device__ __forceinline__ void cp_wait1()  { asm volatile("cp.async.wait_group 1;" ::: "memory"); }

#define PSTRIDE 68                                   // 68*4 = 272 B (16B-aligned rows)
#define STAGE_U32 ((128 + 64) * PSTRIDE)             // floats per pipeline stage
#define GSM_BYTES (2 * STAGE_U32 * 4)                // 104448 B (2-stage)

// ---------------------------------------------------------------------------
// Shared GEMM core (tf32 mma): C[cm0+m, cn0+n] = sum_k A[(m0+m)*rowMul, k] *
// B[n, k] + bias[n].  BM=128, BN=64, BK=64, 256 threads = 8 warps (4M x 2N).
// cp.async 2-stage smem pipeline (raw fp32 staged; tf32 cvt at fragment load
// — numerically identical to cvt-at-stage). launch_bounds(256,2) -> <=128
// regs -> 2 CTAs/SM.
// ---------------------------------------------------------------------------
__device__ __forceinline__ void gemm_core(
    const float* __restrict__ Ab, int lda, int rowMul, int m0,
    const float* __restrict__ Bb, int ldb,
    const float* __restrict__ biasb,
    float* __restrict__ Cb, int ldc, int cm0, int cn0, int K,
    float* smem, uint32_t smem_u32)
{
    const int tid  = threadIdx.x;
    const int wid  = tid >> 5;
    const int lane = tid & 31;
    const int g    = lane >> 2;
    const int tc   = lane & 3;
    const int wm   = wid & 3;
    const int wn   = wid >> 2;

    auto copy_chunk = [&](int buf, int k0) {
        uint32_t abase = smem_u32 + buf * (STAGE_U32 * 4);
        uint32_t bbase = abase + 128 * PSTRIDE * 4;
        #pragma unroll
        for (int it = 0; it < 8; it++) {
            int i = tid + it * 256;
            int r = i >> 4, cc = (i & 15) << 2;
            cp16(abase + (r * PSTRIDE + cc) * 4,
                 Ab + (long)(m0 + r) * rowMul * lda + k0 + cc);
        }
        #pragma unroll
        for (int it = 0; it < 4; it++) {
            int i = tid + it * 256;
            int r = i >> 4, cc = (i & 15) << 2;
            cp16(bbase + (r * PSTRIDE + cc) * 4,
                 Bb + (long)r * ldb + k0 + cc);
        }
        cp_commit();
    };

    float acc[2][4][4];
    #pragma unroll
    for (int mt = 0; mt < 2; mt++)
        #pragma unroll
        for (int nt = 0; nt < 4; nt++)
            #pragma unroll
            for (int i = 0; i < 4; i++) acc[mt][nt][i] = 0.f;

    const int NCH = K / 64;
    copy_chunk(0, 0);

    for (int ch = 0; ch < NCH; ch++) {
        if (ch + 1 < NCH) {
            copy_chunk((ch + 1) & 1, (ch + 1) * 64);   // overlaps with compute(ch)
            cp_wait1();                                 // chunk ch landed
        } else {
            cp_wait0();
        }
        __syncthreads();

        const float* Asf = smem + (ch & 1) * STAGE_U32;
        const float* Bsf = Asf + 128 * PSTRIDE;

        #pragma unroll
        for (int ks = 0; ks < 8; ks++) {
            const int kb = ks * 8;
            uint32_t a[2][4], b[4][2];
            #pragma unroll
            for (int mt = 0; mt < 2; mt++) {
                int row = wm * 32 + mt * 16;
                a[mt][0] = f2tf(Asf[(row + g) * PSTRIDE + kb + tc]);
                a[mt][1] = f2tf(Asf[(row + 8 + g) * PSTRIDE + kb + tc]);
                a[mt][2] = f2tf(Asf[(row + g) * PSTRIDE + kb + tc + 4]);
                a[mt][3] = f2tf(Asf[(row + 8 + g) * PSTRIDE + kb + tc + 4]);
            }
            #pragma unroll
            for (int nt = 0; nt < 4; nt++) {
                int col = wn * 32 + nt * 8;
                b[nt][0] = f2tf(Bsf[(col + g) * PSTRIDE + kb + tc]);
                b[nt][1] = f2tf(Bsf[(col + g) * PSTRIDE + kb + tc + 4]);
            }
            #pragma unroll
            for (int mt = 0; mt < 2; mt++)
                #pragma unroll
                for (int nt = 0; nt < 4; nt++)
                    mma8(acc[mt][nt], a[mt], b[nt]);
        }
        __syncthreads();    // all warps done with buffer (ch&1) before refill
    }

    #pragma unroll
    for (int mt = 0; mt < 2; mt++) {
        #pragma unroll
        for (int nt = 0; nt < 4; nt++) {
            int lrow = wm * 32 + mt * 16 + g;
            int lcol = wn * 32 + nt * 8 + 2 * tc;
            float bx = biasb[lcol], by = biasb[lcol + 1];
            float2 v0 = { acc[mt][nt][0] + bx, acc[mt][nt][1] + by };
            float2 v1 = { acc[mt][nt][2] + bx, acc[mt][nt][3] + by };
            *(float2*)(Cb + (long)(cm0 + lrow) * ldc + cn0 + lcol) = v0;
            *(float2*)(Cb + (long)(cm0 + lrow + 8) * ldc + cn0 + lcol) = v1;
        }
    }
}

// ---------------------------------------------------------------------------
// Merged Q+K+V projection: 256 blocks.
//   b in [0,128): Q  — m-tile b>>4, n-tile b&15      (M=1024, N=1024)
//   b in [128,192): K-gather — head (b-128)>>2, m-tile (b-128)&3 (M=512, N=64)
//   b in [192,256): V-gather — same layout
// ---------------------------------------------------------------------------
__global__ __launch_bounds__(256, 2)
void qkv_mma(const float* __restrict__ q,  const float* __restrict__ Wq,
             const float* __restrict__ bq,
             const float* __restrict__ k,  const float* __restrict__ Wk,
             const float* __restrict__ bk,
             const float* __restrict__ v,  const float* __restrict__ Wv,
             const float* __restrict__ bv,
             float* __restrict__ Qp, float* __restrict__ Kg,
             float* __restrict__ Vg)
{
    extern __shared__ float gsm[];
    uint32_t su = (uint32_t)__cvta_generic_to_shared(gsm);

    const int b = blockIdx.x;
    const float *Ab, *Bb, *biasb;
    float* Cb;
    int rowMul, m0, cn0, ldc;

    if (b < 128) {
        int mt = b >> 4, nt = b & 15;
        Ab = q;  rowMul = 1;  m0 = mt * 128;
        cn0 = nt * 64;
        Bb = Wq + (long)cn0 * CD;  biasb = bq + cn0;
        Cb = Qp; ldc = CD;
    } else if (b < 192) {
        int idx = b - 128, h = idx >> 2, mt = idx & 3;
        Ab = k + (long)h * CD;  rowMul = 16;  m0 = mt * 128;
        cn0 = 0;
        Bb = Wk + (long)h * HD * CD;  biasb = bk + h * HD;
        Cb = Kg + (long)h * NKEY * HD; ldc = HD;
    } else {
        int idx = b - 192, h = idx >> 2, mt = idx & 3;
        Ab = v + (long)h * CD;  rowMul = 16;  m0 = mt * 128;
        cn0 = 0;
        Bb = Wv + (long)h * HD * CD;  biasb = bv + h * HD;
        Cb = Vg + (long)h * NKEY * HD; ldc = HD;
    }

    gemm_core(Ab, CD, rowMul, m0, Bb, CD, biasb, Cb, ldc, m0, cn0, CD, gsm, su);
}

// ---------------------------------------------------------------------------
// Output projection (standalone): out = AO @ Wo^T + bo
// ---------------------------------------------------------------------------
__global__ __launch_bounds__(256, 2)
void gemm_mma(const float* __restrict__ A,
              const float* __restrict__ B,
              const float* __restrict__ bias,
              float* __restrict__ C)
{
    extern __shared__ float gsm[];
    uint32_t su = (uint32_t)__cvta_generic_to_shared(gsm);
    const int m0 = blockIdx.y * 128;
    const int n0 = blockIdx.x * 64;
    gemm_core(A, CD, 1, m0, B + (long)n0 * CD, CD, bias + n0,
              C, CD, m0, n0, CD, gsm, su);
}

// ---------------------------------------------------------------------------
// Fused attention, split-K (unchanged from R9): block = 32 queries x 1 head;
// 4 warps = 2 query-groups x 2 key-halves; flash-style merge at the end.
// ---------------------------------------------------------------------------
__global__ __launch_bounds__(128)
void attn_mma(const float* __restrict__ Qp, const float* __restrict__ Kg,
              const float* __restrict__ Vg, float* __restrict__ AO)
{
    extern __shared__ uint32_t asm_[];
    uint32_t* KVs = asm_;                  // [2][64*68]
    uint32_t* Ps  = asm_ + 2 * 64 * 68;    // [2][32*68]

    const int h    = blockIdx.y;
    const int q0   = blockIdx.x * 32;
    const int tid  = threadIdx.x;
    const int wid  = tid >> 5;
    const int lane = tid & 31;
    const int g    = lane >> 2;
    const int tc   = lane & 3;
    const int qg   = wid & 1;
    const int half = wid >> 1;
    const int s    = tid & 63;

    uint32_t* KVh = KVs + half * 64 * 68;
    uint32_t* Psh = Ps  + half * 32 * 68;

    const float* Qb = Qp + (long)(q0 + qg * 16) * CD + h * HD;
    const float* Kb = Kg + (long)h * NKEY * HD + (long)half * 256 * HD;
    const float* Vb = Vg + (long)h * NKEY * HD + (long)half * 256 * HD;

    uint32_t qa[8][4];
    #pragma unroll
    for (int ks = 0; ks < 8; ks++) {
        qa[ks][0] = f2tf(Qb[(long)g * CD + ks * 8 + tc]);
        qa[ks][1] = f2tf(Qb[(long)(g + 8) * CD + ks * 8 + tc]);
        qa[ks][2] = f2tf(Qb[(long)g * CD + ks * 8 + tc + 4]);
        qa[ks][3] = f2tf(Qb[(long)(g + 8) * CD + ks * 8 + tc + 4]);
    }

    float o[8][4];
    #pragma unroll
    for (int nt = 0; nt < 8; nt++)
        #pragma unroll
        for (int i = 0; i < 4; i++) o[nt][i] = 0.f;
    float m0_ = -1e30f, m1_ = -1e30f, s0 = 0.f, s1 = 0.f;

    for (int it = 0; it < 4; it++) {
        const int c0 = it * 64;
        __syncthreads();
        for (int i = s; i < 64 * 16; i += 64) {
            int r = i >> 4, cc = (i & 15) << 2;
            float4 t = *(const float4*)(Kb + (long)(c0 + r) * HD + cc);
            uint32_t* d = &KVh[r * 68 + cc];
            d[0] = f2tf(t.x); d[1] = f2tf(t.y); d[2] = f2tf(t.z); d[3] = f2tf(t.w);
        }
        __syncthreads();

        float sc[8][4];
        #pragma unroll
        for (int nt = 0; nt < 8; nt++)
            #pragma unroll
            for (int i = 0; i < 4; i++) sc[nt][i] = 0.f;
        #pragma unroll
        for (int ks = 0; ks < 8; ks++) {
            #pragma unroll
            for (int nt = 0; nt < 8; nt++) {
                uint32_t b[2];
                b[0] = KVh[(nt * 8 + g) * 68 + ks * 8 + tc];
                b[1] = KVh[(nt * 8 + g) * 68 + ks * 8 + tc + 4];
                mma8(sc[nt], qa[ks], b);
            }
        }

        float mx0 = -1e30f, mx1 = -1e30f;
        #pragma unroll
        for (int nt = 0; nt < 8; nt++) {
            sc[nt][0] *= 0.125f; sc[nt][1] *= 0.125f;
            sc[nt][2] *= 0.125f; sc[nt][3] *= 0.125f;
            mx0 = fmaxf(mx0, fmaxf(sc[nt][0], sc[nt][1]));
            mx1 = fmaxf(mx1, fmaxf(sc[nt][2], sc[nt][3]));
        }
        mx0 = fmaxf(mx0, __shfl_xor_sync(0xffffffffu, mx0, 1));
        mx0 = fmaxf(mx0, __shfl_xor_sync(0xffffffffu, mx0, 2));
        mx1 = fmaxf(mx1, __shfl_xor_sync(0xffffffffu, mx1, 1));
        mx1 = fmaxf(mx1, __shfl_xor_sync(0xffffffffu, mx1, 2));
        float mn0 = fmaxf(m0_, mx0), mn1 = fmaxf(m1_, mx1);
        float f0 = __expf(m0_ - mn0), f1 = __expf(m1_ - mn1);
        m0_ = mn0; m1_ = mn1;
        float sum0 = 0.f, sum1 = 0.f;
        #pragma unroll
        for (int nt = 0; nt < 8; nt++) {
            sc[nt][0] = __expf(sc[nt][0] - mn0);
            sc[nt][1] = __expf(sc[nt][1] - mn0);
            sc[nt][2] = __expf(sc[nt][2] - mn1);
            sc[nt][3] = __expf(sc[nt][3] - mn1);
            sum0 += sc[nt][0] + sc[nt][1];
            sum1 += sc[nt][2] + sc[nt][3];
            int col = nt * 8 + 2 * tc;
            Psh[(qg * 16 + g) * 68 + col]     = f2tf(sc[nt][0]);
            Psh[(qg * 16 + g) * 68 + col + 1] = f2tf(sc[nt][1]);
            Psh[(qg * 16 + 8 + g) * 68 + col]     = f2tf(sc[nt][2]);
            Psh[(qg * 16 + 8 + g) * 68 + col + 1] = f2tf(sc[nt][3]);
        }
        sum0 += __shfl_xor_sync(0xffffffffu, sum0, 1);
        sum0 += __shfl_xor_sync(0xffffffffu, sum0, 2);
        sum1 += __shfl_xor_sync(0xffffffffu, sum1, 1);
        sum1 += __shfl_xor_sync(0xffffffffu, sum1, 2);
        s0 = s0 * f0 + sum0;
        s1 = s1 * f1 + sum1;
        __syncthreads();

        for (int i = s; i < 64 * 16; i += 64) {
            int r = i >> 4, cc = (i & 15) << 2;
            float4 t = *(const float4*)(Vb + (long)(c0 + r) * HD + cc);
            KVh[(cc + 0) * 68 + r] = f2tf(t.x);
            KVh[(cc + 1) * 68 + r] = f2tf(t.y);
            KVh[(cc + 2) * 68 + r] = f2tf(t.z);
            KVh[(cc + 3) * 68 + r] = f2tf(t.w);
        }
        #pragma unroll
        for (int nt = 0; nt < 8; nt++) {
            o[nt][0] *= f0; o[nt][1] *= f0;
            o[nt][2] *= f1; o[nt][3] *= f1;
        }
        __syncthreads();

        #pragma unroll
        for (int ks = 0; ks < 8; ks++) {
            uint32_t pa[4];
            pa[0] = Psh[(qg * 16 + g) * 68 + ks * 8 + tc];
            pa[1] = Psh[(qg * 16 + 8 + g) * 68 + ks * 8 + tc];
            pa[2] = Psh[(qg * 16 + g) * 68 + ks * 8 + tc + 4];
            pa[3] = Psh[(qg * 16 + 8 + g) * 68 + ks * 8 + tc + 4];
            #pragma unroll
            for (int nt = 0; nt < 8; nt++) {
                uint32_t b[2];
                b[0] = KVh[(nt * 8 + g) * 68 + ks * 8 + tc];
                b[1] = KVh[(nt * 8 + g) * 68 + ks * 8 + tc + 4];
                mma8(o[nt], pa, b);
            }
        }
    }

    __syncthreads();
    float* Osm = (float*)Ps;
    float* MS  = (float*)(Ps + 32 * 68);

    const int row0 = qg * 16 + g;
    const int row1 = row0 + 8;

    if (half == 1) {
        if (tc == 0) {
            MS[row0 * 2] = m0_;  MS[row0 * 2 + 1] = s0;
            MS[row1 * 2] = m1_;  MS[row1 * 2 + 1] = s1;
        }
        #pragma unroll
        for (int nt = 0; nt < 8; nt++) {
            int col = nt * 8 + 2 * tc;
            Osm[row0 * 68 + col]     = o[nt][0];
            Osm[row0 * 68 + col + 1] = o[nt][1];
            Osm[row1 * 68 + col]     = o[nt][2];
            Osm[row1 * 68 + col + 1] = o[nt][3];
        }
    }
    __syncthreads();

    if (half == 0) {
        float mB0 = MS[row0 * 2], sB0 = MS[row0 * 2 + 1];
        float mB1 = MS[row1 * 2], sB1 = MS[row1 * 2 + 1];
        float mM0 = fmaxf(m0_, mB0), mM1 = fmaxf(m1_, mB1);
        float eA0 = __expf(m0_ - mM0), eB0 = __expf(mB0 - mM0);
        float eA1 = __expf(m1_ - mM1), eB1 = __expf(mB1 - mM1);
        float inv0 = 1.f / (s0 * eA0 + sB0 * eB0);
        float inv1 = 1.f / (s1 * eA1 + sB1 * eB1);
        #pragma unroll
        for (int nt = 0; nt < 8; nt++) {
            int col = nt * 8 + 2 * tc;
            float2 v0, v1;
            v0.x = (o[nt][0] * eA0 + Osm[row0 * 68 + col]     * eB0) * inv0;
            v0.y = (o[nt][1] * eA0 + Osm[row0 * 68 + col + 1] * eB0) * inv0;
            v1.x = (o[nt][2] * eA1 + Osm[row1 * 68 + col]     * eB1) * inv1;
            v1.y = (o[nt][3] * eA1 + Osm[row1 * 68 + col + 1] * eB1) * inv1;
            *(float2*)(AO + (long)(q0 + row0) * CD + h * HD + col) = v0;
            *(float2*)(AO + (long)(q0 + row1) * CD + h * HD + col) = v1;
        }
    }
}

#define ATT_SM_BYTES ((2 * 64 * 68 + 2 * 32 * 68) * 4)   // 52224

// ---------------------------------------------------------------------------
// Launch
// ---------------------------------------------------------------------------
extern "C" void kernel_launch(void* const* d_in, const int* in_sizes, int n_in,
                              void* d_out, int out_size)
{
    (void)in_sizes; (void)n_in; (void)out_size;
    const float* q  = (const float*)d_in[0];
    const float* k  = (const float*)d_in[1];
    const float* v  = (const float*)d_in[2];
    const float* Wq = (const float*)d_in[3];
    const float* bq = (const float*)d_in[4];
    const float* Wk = (const float*)d_in[5];
    const float* bk = (const float*)d_in[6];
    const float* Wv = (const float*)d_in[7];
    const float* bv = (const float*)d_in[8];
    const float* Wo = (const float*)d_in[9];
    const float* bo = (const float*)d_in[10];
    float* out = (float*)d_out;

    float *Qp, *Kg, *Vg, *AO;
    cudaGetSymbolAddress((void**)&Qp, g_Qp);
    cudaGetSymbolAddress((void**)&Kg, g_Kg);
    cudaGetSymbolAddress((void**)&Vg, g_Vg);
    cudaGetSymbolAddress((void**)&AO, g_AO);

    cudaFuncSetAttribute(qkv_mma,  cudaFuncAttributeMaxDynamicSharedMemorySize, GSM_BYTES);
    cudaFuncSetAttribute(gemm_mma, cudaFuncAttributeMaxDynamicSharedMemorySize, GSM_BYTES);
    cudaFuncSetAttribute(attn_mma, cudaFuncAttributeMaxDynamicSharedMemorySize, ATT_SM_BYTES);

    // 1) Merged Q + K-gather + V-gather projections — 256 blocks, 2 CTA/SM
    qkv_mma<<<256, 256, GSM_BYTES>>>(q, Wq, bq, k, Wk, bk, v, Wv, bv, Qp, Kg, Vg);

    // 2) Fused split-K attention — 512 blocks x 128 threads
    attn_mma<<<dim3(TQN / 32, NH), 128, ATT_SM_BYTES>>>(Qp, Kg, Vg, AO);

    // 3) Output projection — 128 blocks, 2 CTA/SM
    gemm_mma<<<dim3(CD / 64, TQN / 128), 256, GSM_BYTES>>>(AO, Wo, bo, out);
}

// round 11
// speedup vs baseline: 1.3548x; 1.3548x over previous
#include <cuda_runtime.h>
#include <cuda_fp16.h>
#include <cstdint>

// Problem constants
#define CD    1024   // d_model
#define TQN   1024   // query tokens
#define NH    16     // heads
#define HD    64     // head dim
#define NKEY  512    // keys per head after HEPOS gather (8192/16)

#define AST   72     // smem row stride in halves (64 + 8 pad; 36 words -> conflict-free)

// ---------------------------------------------------------------------------
// Scratch (device globals; runtime allocation is forbidden)
// ---------------------------------------------------------------------------
__device__ __align__(256) float g_Qp[TQN * CD];          // Q projection
__device__ __align__(256) float g_Kg[NH * NKEY * HD];    // gathered/projected K [h][j][d]
__device__ __align__(256) float g_Vg[NH * NKEY * HD];    // gathered/projected V [h][j][d]
__device__ __align__(256) float g_AO[TQN * CD];          // attention output

// ---------------------------------------------------------------------------
// fp16 mma.sync helpers (legacy tensor-core path, base sm_100 target)
// ---------------------------------------------------------------------------
// pack2(lo, hi): f16x2 with lower half = lo  (cvt.rn.f16x2.f32 d,a,b: d.hi=a, d.lo=b)
__device__ __forceinline__ uint32_t pack2(float lo, float hi) {
    uint32_t r;
    asm("cvt.rn.f16x2.f32 %0, %1, %2;" : "=r"(r) : "f"(hi), "f"(lo));
    return r;
}
// D(16x8,f32) += A(16x16,f16) * B(16x8,f16)
__device__ __forceinline__ void mma16(float* c, const uint32_t* a, const uint32_t* b) {
    asm volatile(
        "mma.sync.aligned.m16n8k16.row.col.f32.f16.f16.f32 "
        "{%0,%1,%2,%3}, {%4,%5,%6,%7}, {%8,%9}, {%0,%1,%2,%3};\n"
        : "+f"(c[0]), "+f"(c[1]), "+f"(c[2]), "+f"(c[3])
        : "r"(a[0]), "r"(a[1]), "r"(a[2]), "r"(a[3]), "r"(b[0]), "r"(b[1]));
}

// ---------------------------------------------------------------------------
// Shared GEMM core (fp16 mma): C[cm0+m, cn0+n] = sum_k A[(m0+m)*rowMul, k] *
// B[n, k] + bias[n].  BM=128, BN=64, BK=64, 256 threads = 8 warps (4M x 2N),
// warp tile 32x32, register-prefetch software pipeline, cvt f32->f16x2 at
// stage time (1 instr / 2 elems). 4 k-steps of 16 per chunk.
// ---------------------------------------------------------------------------
__device__ __forceinline__ void gemm_core(
    const float* __restrict__ Ab, int lda, int rowMul, int m0,
    const float* __restrict__ Bb, int ldb,
    const float* __restrict__ biasb,
    float* __restrict__ Cb, int ldc, int cm0, int cn0, int K,
    uint16_t* As2, uint16_t* Bs2)
{
    const int tid  = threadIdx.x;
    const int wid  = tid >> 5;
    const int lane = tid & 31;
    const int g    = lane >> 2;
    const int tc   = lane & 3;
    const int wm   = wid & 3;
    const int wn   = wid >> 2;

    float4 areg[8], breg[4];
    auto ldg_chunk = [&](int k0) {
        #pragma unroll
        for (int it = 0; it < 8; it++) {
            int i = tid + it * 256;
            int r = i >> 4, cc = (i & 15) << 2;
            areg[it] = *(const float4*)(Ab + (long)(m0 + r) * rowMul * lda + k0 + cc);
        }
        #pragma unroll
        for (int it = 0; it < 4; it++) {
            int i = tid + it * 256;
            int r = i >> 4, cc = (i & 15) << 2;
            breg[it] = *(const float4*)(Bb + (long)r * ldb + k0 + cc);
        }
    };
    auto sts_chunk = [&]() {
        #pragma unroll
        for (int it = 0; it < 8; it++) {
            int i = tid + it * 256;
            int r = i >> 4, cc = (i & 15) << 2;
            uint32_t* d = (uint32_t*)&As2[r * AST + cc];
            d[0] = pack2(areg[it].x, areg[it].y);
            d[1] = pack2(areg[it].z, areg[it].w);
        }
        #pragma unroll
        for (int it = 0; it < 4; it++) {
            int i = tid + it * 256;
            int r = i >> 4, cc = (i & 15) << 2;
            uint32_t* d = (uint32_t*)&Bs2[r * AST + cc];
            d[0] = pack2(breg[it].x, breg[it].y);
            d[1] = pack2(breg[it].z, breg[it].w);
        }
    };

    float acc[2][4][4];
    #pragma unroll
    for (int mt = 0; mt < 2; mt++)
        #pragma unroll
        for (int nt = 0; nt < 4; nt++)
            #pragma unroll
            for (int i = 0; i < 4; i++) acc[mt][nt][i] = 0.f;

    const int NCH = K / 64;
    ldg_chunk(0);

    for (int ch = 0; ch < NCH; ch++) {
        __syncthreads();
        sts_chunk();
        __syncthreads();
        if (ch + 1 < NCH) ldg_chunk((ch + 1) * 64);

        #pragma unroll
        for (int ks = 0; ks < 4; ks++) {          // K=16 per step
            const int kb = ks * 16;
            uint32_t a[2][4], b[4][2];
            #pragma unroll
            for (int mt = 0; mt < 2; mt++) {
                int row = wm * 32 + mt * 16;
                a[mt][0] = *(const uint32_t*)&As2[(row + g) * AST + kb + 2 * tc];
                a[mt][1] = *(const uint32_t*)&As2[(row + 8 + g) * AST + kb + 2 * tc];
                a[mt][2] = *(const uint32_t*)&As2[(row + g) * AST + kb + 2 * tc + 8];
                a[mt][3] = *(const uint32_t*)&As2[(row + 8 + g) * AST + kb + 2 * tc + 8];
            }
            #pragma unroll
            for (int nt = 0; nt < 4; nt++) {
                int col = wn * 32 + nt * 8;
                b[nt][0] = *(const uint32_t*)&Bs2[(col + g) * AST + kb + 2 * tc];
                b[nt][1] = *(const uint32_t*)&Bs2[(col + g) * AST + kb + 2 * tc + 8];
            }
            #pragma unroll
            for (int mt = 0; mt < 2; mt++)
                #pragma unroll
                for (int nt = 0; nt < 4; nt++)
                    mma16(acc[mt][nt], a[mt], b[nt]);
        }
    }

    #pragma unroll
    for (int mt = 0; mt < 2; mt++) {
        #pragma unroll
        for (int nt = 0; nt < 4; nt++) {
            int lrow = wm * 32 + mt * 16 + g;
            int lcol = wn * 32 + nt * 8 + 2 * tc;
            float bx = biasb[lcol], by = biasb[lcol + 1];
            float2 v0 = { acc[mt][nt][0] + bx, acc[mt][nt][1] + by };
            float2 v1 = { acc[mt][nt][2] + bx, acc[mt][nt][3] + by };
            *(float2*)(Cb + (long)(cm0 + lrow) * ldc + cn0 + lcol) = v0;
            *(float2*)(Cb + (long)(cm0 + lrow + 8) * ldc + cn0 + lcol) = v1;
        }
    }
}

// ---------------------------------------------------------------------------
// Merged Q+K+V projection: 256 blocks (Q: 128, K-gather: 64, V-gather: 64).
// ---------------------------------------------------------------------------
__global__ __launch_bounds__(256)
void qkv_mma(const float* __restrict__ q,  const float* __restrict__ Wq,
             const float* __restrict__ bq,
             const float* __restrict__ k,  const float* __restrict__ Wk,
             const float* __restrict__ bk,
             const float* __restrict__ v,  const float* __restrict__ Wv,
             const float* __restrict__ bv,
             float* __restrict__ Qp, float* __restrict__ Kg,
             float* __restrict__ Vg)
{
    __shared__ __align__(16) uint16_t As2[128 * AST];   // 18432 B
    __shared__ __align__(16) uint16_t Bs2[64 * AST];    //  9216 B

    const int b = blockIdx.x;
    const float *Ab, *Bb, *biasb;
    float* Cb;
    int rowMul, m0, cn0, ldc;

    if (b < 128) {
        int mt = b >> 4, nt = b & 15;
        Ab = q;  rowMul = 1;  m0 = mt * 128;
        cn0 = nt * 64;
        Bb = Wq + (long)cn0 * CD;  biasb = bq + cn0;
        Cb = Qp; ldc = CD;
    } else if (b < 192) {
        int idx = b - 128, h = idx >> 2, mt = idx & 3;
        Ab = k + (long)h * CD;  rowMul = 16;  m0 = mt * 128;
        cn0 = 0;
        Bb = Wk + (long)h * HD * CD;  biasb = bk + h * HD;
        Cb = Kg + (long)h * NKEY * HD; ldc = HD;
    } else {
        int idx = b - 192, h = idx >> 2, mt = idx & 3;
        Ab = v + (long)h * CD;  rowMul = 16;  m0 = mt * 128;
        cn0 = 0;
        Bb = Wv + (long)h * HD * CD;  biasb = bv + h * HD;
        Cb = Vg + (long)h * NKEY * HD; ldc = HD;
    }

    gemm_core(Ab, CD, rowMul, m0, Bb, CD, biasb, Cb, ldc, m0, cn0, CD, As2, Bs2);
}

// ---------------------------------------------------------------------------
// Output projection: out = AO @ Wo^T + bo
// ---------------------------------------------------------------------------
__global__ __launch_bounds__(256)
void gemm_mma(const float* __restrict__ A,
              const float* __restrict__ B,
              const float* __restrict__ bias,
              float* __restrict__ C)
{
    __shared__ __align__(16) uint16_t As2[128 * AST];
    __shared__ __align__(16) uint16_t Bs2[64 * AST];
    const int m0 = blockIdx.y * 128;
    const int n0 = blockIdx.x * 64;
    gemm_core(A, CD, 1, m0, B + (long)n0 * CD, CD, bias + n0,
              C, CD, m0, n0, CD, As2, Bs2);
}

// ---------------------------------------------------------------------------
// Fused attention, split-K, fp16 mma: block = 32 queries x 1 head; 4 warps =
// 2 query-groups x 2 key-halves (256 keys each); flash-style merge at end.
// Static smem: KV 2x64xAST halves + P 2x32xAST halves + merge scratch.
// ---------------------------------------------------------------------------
__global__ __launch_bounds__(128)
void attn_mma(const float* __restrict__ Qp, const float* __restrict__ Kg,
              const float* __restrict__ Vg, float* __restrict__ AO)
{
    __shared__ __align__(16) uint16_t KVs2[2][64 * AST];   // 18432 B
    __shared__ __align__(16) uint16_t Ps2[2][32 * AST];    //  9216 B
    __shared__ float Osm[32 * 68];                         //  8704 B
    __shared__ float MS[32 * 2];                           //   256 B

    const int h    = blockIdx.y;
    const int q0   = blockIdx.x * 32;
    const int tid  = threadIdx.x;
    const int wid  = tid >> 5;
    const int lane = tid & 31;
    const int g    = lane >> 2;
    const int tc   = lane & 3;
    const int qg   = wid & 1;       // query group (rows qg*16 .. qg*16+15)
    const int half = wid >> 1;      // key half (0: keys 0..255, 1: 256..511)
    const int s    = tid & 63;      // staging index within half

    uint16_t* KVh = KVs2[half];
    uint16_t* Psh = Ps2[half];

    const float* Qb = Qp + (long)(q0 + qg * 16) * CD + h * HD;
    const float* Kb = Kg + (long)h * NKEY * HD + (long)half * 256 * HD;
    const float* Vb = Vg + (long)h * NKEY * HD + (long)half * 256 * HD;

    // Q fragments in registers: 4 k-steps of 16 over d=64
    uint32_t qa[4][4];
    #pragma unroll
    for (int ks = 0; ks < 4; ks++) {
        int kb = ks * 16;
        qa[ks][0] = pack2(Qb[(long)g * CD + kb + 2 * tc],
                          Qb[(long)g * CD + kb + 2 * tc + 1]);
        qa[ks][1] = pack2(Qb[(long)(g + 8) * CD + kb + 2 * tc],
                          Qb[(long)(g + 8) * CD + kb + 2 * tc + 1]);
        qa[ks][2] = pack2(Qb[(long)g * CD + kb + 2 * tc + 8],
                          Qb[(long)g * CD + kb + 2 * tc + 9]);
        qa[ks][3] = pack2(Qb[(long)(g + 8) * CD + kb + 2 * tc + 8],
                          Qb[(long)(g + 8) * CD + kb + 2 * tc + 9]);
    }

    float o[8][4];
    #pragma unroll
    for (int nt = 0; nt < 8; nt++)
        #pragma unroll
        for (int i = 0; i < 4; i++) o[nt][i] = 0.f;
    float m0_ = -1e30f, m1_ = -1e30f, s0 = 0.f, s1 = 0.f;

    for (int it = 0; it < 4; it++) {       // 4 chunks of 64 keys per half
        const int c0 = it * 64;
        __syncthreads();
        // Stage K chunk [key][d] as f16
        for (int i = s; i < 64 * 16; i += 64) {
            int r = i >> 4, cc = (i & 15) << 2;
            float4 t = *(const float4*)(Kb + (long)(c0 + r) * HD + cc);
            uint32_t* d = (uint32_t*)&KVh[r * AST + cc];
            d[0] = pack2(t.x, t.y);
            d[1] = pack2(t.z, t.w);
        }
        __syncthreads();

        // S = Q.K^T : 16q x 64key per warp, 4 k-steps of 16
        float sc[8][4];
        #pragma unroll
        for (int nt = 0; nt < 8; nt++)
            #pragma unroll
            for (int i = 0; i < 4; i++) sc[nt][i] = 0.f;
        #pragma unroll
        for (int ks = 0; ks < 4; ks++) {
            const int kb = ks * 16;
            #pragma unroll
            for (int nt = 0; nt < 8; nt++) {
                uint32_t b[2];
                b[0] = *(const uint32_t*)&KVh[(nt * 8 + g) * AST + kb + 2 * tc];
                b[1] = *(const uint32_t*)&KVh[(nt * 8 + g) * AST + kb + 2 * tc + 8];
                mma16(sc[nt], qa[ks], b);
            }
        }

        // Online softmax (rows r0 = qg*16+g -> c0/c1, r1 = r0+8 -> c2/c3)
        float mx0 = -1e30f, mx1 = -1e30f;
        #pragma unroll
        for (int nt = 0; nt < 8; nt++) {
            sc[nt][0] *= 0.125f; sc[nt][1] *= 0.125f;
            sc[nt][2] *= 0.125f; sc[nt][3] *= 0.125f;
            mx0 = fmaxf(mx0, fmaxf(sc[nt][0], sc[nt][1]));
            mx1 = fmaxf(mx1, fmaxf(sc[nt][2], sc[nt][3]));
        }
        mx0 = fmaxf(mx0, __shfl_xor_sync(0xffffffffu, mx0, 1));
        mx0 = fmaxf(mx0, __shfl_xor_sync(0xffffffffu, mx0, 2));
        mx1 = fmaxf(mx1, __shfl_xor_sync(0xffffffffu, mx1, 1));
        mx1 = fmaxf(mx1, __shfl_xor_sync(0xffffffffu, mx1, 2));
        float mn0 = fmaxf(m0_, mx0), mn1 = fmaxf(m1_, mx1);
        float f0 = __expf(m0_ - mn0), f1 = __expf(m1_ - mn1);
        m0_ = mn0; m1_ = mn1;
        float sum0 = 0.f, sum1 = 0.f;
        #pragma unroll
        for (int nt = 0; nt < 8; nt++) {
            sc[nt][0] = __expf(sc[nt][0] - mn0);
            sc[nt][1] = __expf(sc[nt][1] - mn0);
            sc[nt][2] = __expf(sc[nt][2] - mn1);
            sc[nt][3] = __expf(sc[nt][3] - mn1);
            sum0 += sc[nt][0] + sc[nt][1];
            sum1 += sc[nt][2] + sc[nt][3];
            int col = nt * 8 + 2 * tc;
            *(uint32_t*)&Psh[(qg * 16 + g) * AST + col]     = pack2(sc[nt][0], sc[nt][1]);
            *(uint32_t*)&Psh[(qg * 16 + 8 + g) * AST + col] = pack2(sc[nt][2], sc[nt][3]);
        }
        sum0 += __shfl_xor_sync(0xffffffffu, sum0, 1);
        sum0 += __shfl_xor_sync(0xffffffffu, sum0, 2);
        sum1 += __shfl_xor_sync(0xffffffffu, sum1, 1);
        sum1 += __shfl_xor_sync(0xffffffffu, sum1, 2);
        s0 = s0 * f0 + sum0;
        s1 = s1 * f1 + sum1;
        __syncthreads();

        // Stage V chunk TRANSPOSED [d][key] as f16
        for (int i = s; i < 64 * 16; i += 64) {
            int r = i >> 4, cc = (i & 15) << 2;    // r = key, cc = d
            float4 t = *(const float4*)(Vb + (long)(c0 + r) * HD + cc);
            KVh[(cc + 0) * AST + r] = __half_as_ushort(__float2half_rn(t.x));
            KVh[(cc + 1) * AST + r] = __half_as_ushort(__float2half_rn(t.y));
            KVh[(cc + 2) * AST + r] = __half_as_ushort(__float2half_rn(t.z));
            KVh[(cc + 3) * AST + r] = __half_as_ushort(__float2half_rn(t.w));
        }
        #pragma unroll
        for (int nt = 0; nt < 8; nt++) {
            o[nt][0] *= f0; o[nt][1] *= f0;
            o[nt][2] *= f1; o[nt][3] *= f1;
        }
        __syncthreads();

        // O += P.V : contraction over 64 keys (4 k-steps of 16), n = d
        #pragma unroll
        for (int ks = 0; ks < 4; ks++) {
            const int kb = ks * 16;
            uint32_t pa[4];
            pa[0] = *(const uint32_t*)&Psh[(qg * 16 + g) * AST + kb + 2 * tc];
            pa[1] = *(const uint32_t*)&Psh[(qg * 16 + 8 + g) * AST + kb + 2 * tc];
            pa[2] = *(const uint32_t*)&Psh[(qg * 16 + g) * AST + kb + 2 * tc + 8];
            pa[3] = *(const uint32_t*)&Psh[(qg * 16 + 8 + g) * AST + kb + 2 * tc + 8];
            #pragma unroll
            for (int nt = 0; nt < 8; nt++) {
                uint32_t b[2];
                b[0] = *(const uint32_t*)&KVh[(nt * 8 + g) * AST + kb + 2 * tc];
                b[1] = *(const uint32_t*)&KVh[(nt * 8 + g) * AST + kb + 2 * tc + 8];
                mma16(o[nt], pa, b);
            }
        }
    }

    // ---- Merge key-halves (flash-decode style) ----
    __syncthreads();
    const int row0 = qg * 16 + g;
    const int row1 = row0 + 8;

    if (half == 1) {
        if (tc == 0) {
            MS[row0 * 2] = m0_;  MS[row0 * 2 + 1] = s0;
            MS[row1 * 2] = m1_;  MS[row1 * 2 + 1] = s1;
        }
        #pragma unroll
        for (int nt = 0; nt < 8; nt++) {
            int col = nt * 8 + 2 * tc;
            Osm[row0 * 68 + col]     = o[nt][0];
            Osm[row0 * 68 + col + 1] = o[nt][1];
            Osm[row1 * 68 + col]     = o[nt][2];
            Osm[row1 * 68 + col + 1] = o[nt][3];
        }
    }
    __syncthreads();

    if (half == 0) {
        float mB0 = MS[row0 * 2], sB0 = MS[row0 * 2 + 1];
        float mB1 = MS[row1 * 2], sB1 = MS[row1 * 2 + 1];
        float mM0 = fmaxf(m0_, mB0), mM1 = fmaxf(m1_, mB1);
        float eA0 = __expf(m0_ - mM0), eB0 = __expf(mB0 - mM0);
        float eA1 = __expf(m1_ - mM1), eB1 = __expf(mB1 - mM1);
        float inv0 = 1.f / (s0 * eA0 + sB0 * eB0);
        float inv1 = 1.f / (s1 * eA1 + sB1 * eB1);
        #pragma unroll
        for (int nt = 0; nt < 8; nt++) {
            int col = nt * 8 + 2 * tc;
            float2 v0, v1;
            v0.x = (o[nt][0] * eA0 + Osm[row0 * 68 + col]     * eB0) * inv0;
            v0.y = (o[nt][1] * eA0 + Osm[row0 * 68 + col + 1] * eB0) * inv0;
            v1.x = (o[nt][2] * eA1 + Osm[row1 * 68 + col]     * eB1) * inv1;
            v1.y = (o[nt][3] * eA1 + Osm[row1 * 68 + col + 1] * eB1) * inv1;
            *(float2*)(AO + (long)(q0 + row0) * CD + h * HD + col) = v0;
            *(float2*)(AO + (long)(q0 + row1) * CD + h * HD + col) = v1;
        }
    }
}

// ---------------------------------------------------------------------------
// Launch
// ---------------------------------------------------------------------------
extern "C" void kernel_launch(void* const* d_in, const int* in_sizes, int n_in,
                              void* d_out, int out_size)
{
    (void)in_sizes; (void)n_in; (void)out_size;
    const float* q  = (const float*)d_in[0];
    const float* k  = (const float*)d_in[1];
    const float* v  = (const float*)d_in[2];
    const float* Wq = (const float*)d_in[3];
    const float* bq = (const float*)d_in[4];
    const float* Wk = (const float*)d_in[5];
    const float* bk = (const float*)d_in[6];
    const float* Wv = (const float*)d_in[7];
    const float* bv = (const float*)d_in[8];
    const float* Wo = (const float*)d_in[9];
    const float* bo = (const float*)d_in[10];
    float* out = (float*)d_out;

    float *Qp, *Kg, *Vg, *AO;
    cudaGetSymbolAddress((void**)&Qp, g_Qp);
    cudaGetSymbolAddress((void**)&Kg, g_Kg);
    cudaGetSymbolAddress((void**)&Vg, g_Vg);
    cudaGetSymbolAddress((void**)&AO, g_AO);

    // 1) Merged Q + K-gather + V-gather projections — 256 blocks
    qkv_mma<<<256, 256>>>(q, Wq, bq, k, Wk, bk, v, Wv, bv, Qp, Kg, Vg);

    // 2) Fused split-K attention — 512 blocks x 128 threads
    attn_mma<<<dim3(TQN / 32, NH), 128>>>(Qp, Kg, Vg, AO);

    // 3) Output projection — 128 blocks
    gemm_mma<<<dim3(CD / 64, TQN / 128), 256>>>(AO, Wo, bo, out);
}